// round 6
// baseline (speedup 1.0000x reference)
#include <cuda_runtime.h>
#include <cuda_bf16.h>
#include <math.h>
#include <stdint.h>

#define CC 4096
#define NN 1024
#define CN (CC*NN)
#define KE 12288                 // expanded K = 3*CC (2-split, 3 cross products)
#define NEGV (-1e30f)

// ---------------- device scratch (no allocations allowed) ----------------
__device__ float d_D0[NN*NN];          // masked cos0 (vs known)
__device__ float d_D1[NN*NN];          // masked cos1 (vs generated)
__device__ float d_normG[NN];
__device__ float d_normK[NN];
__device__ float d_meanAcc[4];
__device__ int   d_topI[2][NN][2];
__device__ float d_wfin[8];
// expanded bf16 operands, [n][KE], packed as u32 (2 bf16)
__device__ uint32_t d_Ae [(size_t)NN*KE/2];   // G, A-pattern (b1,b1,b2)
__device__ uint32_t d_BeG[(size_t)NN*KE/2];   // G, B-pattern (b1,b2,b1)
__device__ uint32_t d_BeK[(size_t)NN*KE/2];   // K, B-pattern

// ---------------- helpers -------------------------------------------------
__device__ __forceinline__ uint32_t smem_u32(const void* p) {
    uint32_t a;
    asm("{ .reg .u64 t; cvta.to.shared.u64 t, %1; cvt.u32.u64 %0, t; }" : "=r"(a) : "l"(p));
    return a;
}
__device__ __forceinline__ unsigned short bfu(__nv_bfloat16 h) {
    unsigned short u; __builtin_memcpy(&u, &h, 2); return u;
}
__device__ __forceinline__ void cpa16(uint32_t dst, const void* src) {
    asm volatile("cp.async.cg.shared.global [%0], [%1], 16;" :: "r"(dst), "l"(src));
}
__device__ __forceinline__ void ldsm4(uint32_t* r, uint32_t addr) {
    asm volatile("ldmatrix.sync.aligned.m8n8.x4.shared.b16 {%0,%1,%2,%3}, [%4];"
                 : "=r"(r[0]), "=r"(r[1]), "=r"(r[2]), "=r"(r[3]) : "r"(addr));
}
__device__ __forceinline__ void mma16816(float* c, const uint32_t* a, const uint32_t* b) {
    asm volatile("mma.sync.aligned.m16n8k16.row.col.f32.bf16.bf16.f32 "
                 "{%0,%1,%2,%3}, {%4,%5,%6,%7}, {%8,%9}, {%0,%1,%2,%3};"
                 : "+f"(c[0]), "+f"(c[1]), "+f"(c[2]), "+f"(c[3])
                 : "r"(a[0]), "r"(a[1]), "r"(a[2]), "r"(a[3]), "r"(b[0]), "r"(b[1]));
}

// ---------------- kernel 0: zero accumulators ----------------------------
__global__ void k_init() {
    int t = blockIdx.x * blockDim.x + threadIdx.x;
    if (t < NN) { d_normG[t] = 0.f; d_normK[t] = 0.f; }
    if (t < 4)  d_meanAcc[t] = 0.f;
}

// ---------------- kernel 1: copy inputs to out[0..2CN) + column norms ----
__global__ void k_copynorm(const float* __restrict__ G, const float* __restrict__ K,
                           float* __restrict__ out) {
    int n  = blockIdx.x * 256 + threadIdx.x;
    int c0 = blockIdx.y * 128;
    float sg = 0.f, sk = 0.f;
    #pragma unroll 4
    for (int i = 0; i < 128; i++) {
        int idx = (c0 + i) * NN + n;
        float g = G[idx], k = K[idx];
        out[idx]      = g;
        out[CN + idx] = k;
        sg += g * g;
        sk += k * k;
    }
    atomicAdd(&d_normG[n], sg);
    atomicAdd(&d_normK[n], sk);
}

// ---------------- kernel 1b: transpose + 2-split + K-expansion -----------
// A-pattern per original k: (b1,b1,b2); B-pattern: (b1,b2,b1).
__global__ void k_split(const float* __restrict__ G, const float* __restrict__ K) {
    __shared__ float ts[32][33];
    int z = blockIdx.z;
    const float* src = z ? K : G;
    int n0 = blockIdx.x * 32, c0 = blockIdx.y * 32;
    int tx = threadIdx.x, ty = threadIdx.y;          // 32 x 8
    #pragma unroll
    for (int i = 0; i < 4; i++) {
        int cl = ty + i * 8;
        ts[cl][tx] = src[(size_t)(c0 + cl) * NN + n0 + tx];
    }
    __syncthreads();
    int tid = ty * 32 + tx;
    int nl = tid >> 3;                 // 0..31
    int cb = (tid & 7) * 4;            // 0..28
    size_t rb = ((size_t)(n0 + nl) * KE) >> 1;   // u32 row base
    #pragma unroll
    for (int p = 0; p < 2; p++) {
        int cl = cb + p * 2;                          // even
        float v0 = ts[cl][nl], v1 = ts[cl + 1][nl];
        __nv_bfloat16 h10 = __float2bfloat16_rn(v0);
        __nv_bfloat16 h20 = __float2bfloat16_rn(v0 - __bfloat162float(h10));
        __nv_bfloat16 h11 = __float2bfloat16_rn(v1);
        __nv_bfloat16 h21 = __float2bfloat16_rn(v1 - __bfloat162float(h11));
        uint32_t b10 = bfu(h10), b20 = bfu(h20), b11 = bfu(h11), b21 = bfu(h21);
        size_t o = rb + (size_t)(3 * (c0 + cl)) / 2;
        uint32_t wa0 = b10 | (b10 << 16);
        uint32_t wa1 = b20 | (b11 << 16);
        uint32_t wa2 = b11 | (b21 << 16);
        uint32_t wb0 = b10 | (b20 << 16);
        uint32_t wb1 = b10 | (b11 << 16);
        uint32_t wb2 = b21 | (b11 << 16);
        if (z == 0) {
            d_Ae[o] = wa0;  d_Ae[o + 1] = wa1;  d_Ae[o + 2] = wa2;
            d_BeG[o] = wb0; d_BeG[o + 1] = wb1; d_BeG[o + 2] = wb2;
        } else {
            d_BeK[o] = wb0; d_BeK[o + 1] = wb1; d_BeK[o + 2] = wb2;
        }
    }
}

// ---------------- kernel 2: bf16 mma.sync GEMM, 64x64 warp tiles, splitK2
#define KCHUNK 64
#define NKT    (KE / KCHUNK)          // 192
#define ROWB   144                    // 128B row + 16B pad (conflict-free ldmatrix)
#define TILEB  (128 * ROWB)           // 18432
#define STAGEB (2 * TILEB)            // 36864
#define NSTAGE 4
#define SMEM_GEMM (NSTAGE * STAGEB)   // 147456
#define REDSTRIDE 66                  // padded reduction row stride (floats)

__global__ __launch_bounds__(256)
void k_gemm_mma(const float* __restrict__ flag) {
    extern __shared__ char smem[];
    const uint32_t sb = smem_u32(smem);
    const int tid  = threadIdx.x;
    const int lane = tid & 31;
    const int w    = tid >> 5;
    const int wm   = ((w >> 1) & 1) * 64;   // warp m-origin (2x2 spatial grid)
    const int wn   = (w & 1) * 64;          // warp n-origin
    const int kw   = w >> 2;                // k-group: 0 -> ks{0,1}, 1 -> ks{2,3}

    const int bx = blockIdx.x;
    const int z  = bx >> 6;
    const int m0 = ((bx >> 3) & 7) * 128;
    const int n0 = (bx & 7) * 128;

    // global->smem load mapping: row = tid/2, 4 chunks of 16B
    const int lrow = tid >> 1;
    const int lchq = (tid & 1) * 4;
    const __nv_bfloat16* gA = (const __nv_bfloat16*)d_Ae
        + (size_t)(m0 + lrow) * KE + lchq * 8;
    const __nv_bfloat16* gB = (const __nv_bfloat16*)(z ? d_BeG : d_BeK)
        + (size_t)(n0 + lrow) * KE + lchq * 8;
    const uint32_t sAofs = (uint32_t)(lrow * ROWB + lchq * 16);

    #define ISSUE(kt, s) do {                                                   \
        uint32_t _d = sb + (uint32_t)(s) * STAGEB + sAofs;                      \
        const __nv_bfloat16* _a = gA + (kt) * KCHUNK;                           \
        const __nv_bfloat16* _b = gB + (kt) * KCHUNK;                           \
        cpa16(_d,              _a);      cpa16(_d + 16,          _a + 8);       \
        cpa16(_d + 32,         _a + 16); cpa16(_d + 48,          _a + 24);      \
        cpa16(_d + TILEB,      _b);      cpa16(_d + TILEB + 16,  _b + 8);       \
        cpa16(_d + TILEB + 32, _b + 16); cpa16(_d + TILEB + 48,  _b + 24);      \
    } while (0)

    float acc[4][8][4];
    #pragma unroll
    for (int i = 0; i < 4; i++)
        #pragma unroll
        for (int j = 0; j < 8; j++)
            #pragma unroll
            for (int q = 0; q < 4; q++) acc[i][j][q] = 0.f;

    // ldmatrix lane addresses (within a stage)
    const uint32_t aOff = (uint32_t)((wm + (lane & 7) + ((lane >> 3) & 1) * 8) * ROWB
                                     + ((lane >> 4) & 1) * 16);
    const uint32_t bOff = (uint32_t)TILEB
        + (uint32_t)((wn + (lane & 7) + ((lane >> 4) & 1) * 8) * ROWB
                     + ((lane >> 3) & 1) * 16);

    // prologue: 3 stages
    ISSUE(0, 0); asm volatile("cp.async.commit_group;" ::: "memory");
    ISSUE(1, 1); asm volatile("cp.async.commit_group;" ::: "memory");
    ISSUE(2, 2); asm volatile("cp.async.commit_group;" ::: "memory");

    for (int kt = 0; kt < NKT; kt++) {
        asm volatile("cp.async.wait_group 2;" ::: "memory");
        __syncthreads();
        int ip = kt + 3;
        if (ip < NKT) ISSUE(ip, ip & 3);
        asm volatile("cp.async.commit_group;" ::: "memory");

        const uint32_t stage = sb + (uint32_t)(kt & 3) * STAGEB;
        #pragma unroll
        for (int ksi = 0; ksi < 2; ksi++) {
            const int ks = kw * 2 + ksi;
            uint32_t fa[16], fb[16];
            #pragma unroll
            for (int i = 0; i < 4; i++)
                ldsm4(fa + i * 4, stage + aOff + i * (16 * ROWB) + ks * 32);
            #pragma unroll
            for (int j = 0; j < 4; j++)
                ldsm4(fb + j * 4, stage + bOff + j * (16 * ROWB) + ks * 32);
            #pragma unroll
            for (int i = 0; i < 4; i++)
                #pragma unroll
                for (int j = 0; j < 8; j++)
                    mma16816(acc[i][j], fa + i * 4, fb + (j >> 1) * 4 + (j & 1) * 2);
        }
    }
    asm volatile("cp.async.wait_group 0;" ::: "memory");
    __syncthreads();

    // ---- split-K reduction: warps 4-7 dump acc into padded smem ----
    float* red = (float*)smem;
    const int gid = lane >> 2, tig = lane & 3;
    const int t4 = w & 3;
    if (kw == 1) {
        float* base = red + t4 * (64 * REDSTRIDE);
        #pragma unroll
        for (int i = 0; i < 4; i++)
            #pragma unroll
            for (int half = 0; half < 2; half++) {
                int lr = i * 16 + gid + half * 8;
                float* dst = base + lr * REDSTRIDE;
                #pragma unroll
                for (int j = 0; j < 8; j++) {
                    int lc = j * 8 + tig * 2;
                    *(float2*)&dst[lc] =
                        make_float2(acc[i][j][half * 2], acc[i][j][half * 2 + 1]);
                }
            }
    }
    // norms/flags placed above the reduction area
    float* sNa = (float*)(smem + 4 * 64 * REDSTRIDE * 4);
    float* sNb = sNa + 128;
    float* sfl = sNb + 128;
    if (tid < 128) {
        sNa[tid] = d_normG[m0 + tid];
        sNb[tid] = (z ? d_normG : d_normK)[n0 + tid];
        sfl[tid] = flag[n0 + tid];
    }
    __syncthreads();

    // ---- warps 0-3: add partner partials, cosine + mask, write D ----
    if (kw == 0) {
        float* D = z ? d_D1 : d_D0;
        float* base = red + t4 * (64 * REDSTRIDE);
        #pragma unroll
        for (int i = 0; i < 4; i++)
            #pragma unroll
            for (int half = 0; half < 2; half++) {
                int lr = i * 16 + gid + half * 8;
                const float* src = base + lr * REDSTRIDE;
                float na = sNa[wm + lr];
                float* Drow = D + (size_t)(m0 + wm + lr) * NN + n0;
                #pragma unroll
                for (int j = 0; j < 8; j++) {
                    int lc = j * 8 + tig * 2;
                    int c = wn + lc;
                    float v0 = acc[i][j][half * 2 + 0] + src[lc];
                    float v1 = acc[i][j][half * 2 + 1] + src[lc + 1];
                    float f0 = sfl[c], f1 = sfl[c + 1];
                    bool k0 = z ? (f0 != 0.f) : (f0 == 0.f);
                    bool k1 = z ? (f1 != 0.f) : (f1 == 0.f);
                    float2 o;
                    o.x = k0 ? (v0 / sqrtf(na * sNb[c]))     : NEGV;
                    o.y = k1 ? (v1 / sqrtf(na * sNb[c + 1])) : NEGV;
                    *(float2*)&Drow[c] = o;
                }
            }
    }
    #undef ISSUE
}

// ---------------- kernel 3: top-2 per row (stable ties -> lower index) ---
__device__ __forceinline__ bool better(float va, int ia, float vb, int ib) {
    return (va > vb) || (va == vb && ia < ib);
}
__global__ void k_topk(const float* __restrict__ flag) {
    __shared__ float sv1[256], sv2[256];
    __shared__ int   si1[256], si2[256];
    int b = blockIdx.x;
    int z = b >> 10, row = b & 1023;
    const float* Dr = (z ? d_D1 : d_D0) + (size_t)row * NN;
    int tid = threadIdx.x;

    float v1 = -3.0e38f, v2 = -3.0e38f; int i1 = -1, i2 = -1;
    {
        int c = tid * 4;
        float4 v = *(const float4*)&Dr[c];
        float vv[4] = {v.x, v.y, v.z, v.w};
        #pragma unroll
        for (int j = 0; j < 4; j++) {
            if (better(vv[j], c + j, v1, i1)) { v2 = v1; i2 = i1; v1 = vv[j]; i1 = c + j; }
            else if (better(vv[j], c + j, v2, i2)) { v2 = vv[j]; i2 = c + j; }
        }
    }
    sv1[tid] = v1; si1[tid] = i1; sv2[tid] = v2; si2[tid] = i2;
    __syncthreads();
    for (int s = 128; s > 0; s >>= 1) {
        if (tid < s) {
            float w1 = sv1[tid + s], w2 = sv2[tid + s];
            int   j1 = si1[tid + s], j2 = si2[tid + s];
            float t1, t2; int ti1, ti2;
            if (better(v1, i1, w1, j1)) {
                t1 = v1; ti1 = i1;
                if (better(v2, i2, w1, j1)) { t2 = v2; ti2 = i2; }
                else                        { t2 = w1; ti2 = j1; }
            } else {
                t1 = w1; ti1 = j1;
                if (better(v1, i1, w2, j2)) { t2 = v1; ti2 = i1; }
                else                        { t2 = w2; ti2 = j2; }
            }
            v1 = t1; i1 = ti1; v2 = t2; i2 = ti2;
            sv1[tid] = v1; si1[tid] = i1; sv2[tid] = v2; si2[tid] = i2;
        }
        __syncthreads();
    }
    if (tid == 0) {
        d_topI[z][row][0] = i1; d_topI[z][row][1] = i2;
        if (flag[row] != 0.f) {
            atomicAdd(&d_meanAcc[z * 2 + 0], v1);
            atomicAdd(&d_meanAcc[z * 2 + 1], v2);
        }
    }
}

// ---------------- kernel 4: softmax weights + row-0 dup artifact ---------
__global__ void k_finalize(const float* __restrict__ flag) {
    __shared__ float sr[256];
    int tid = threadIdx.x;
    float s = 0.f;
    #pragma unroll
    for (int j = 0; j < 4; j++) s += flag[j * 256 + tid];
    sr[tid] = s; __syncthreads();
    for (int st = 128; st > 0; st >>= 1) {
        if (tid < st) sr[tid] += sr[tid + st];
        __syncthreads();
    }
    if (tid == 0) {
        float nm = sr[0];
        float means[4], mx = -3.0e38f;
        for (int i = 0; i < 4; i++) { means[i] = d_meanAcc[i] / nm; mx = fmaxf(mx, means[i]); }
        float e[4], Z = 0.f;
        for (int i = 0; i < 4; i++) { e[i] = expf(means[i] - mx); Z += e[i]; }
        float f0 = flag[0];
        for (int i = 0; i < 4; i++) {
            float w = e[i] / Z;
            int zz = i >> 1, jj = i & 1;
            int col0 = d_topI[zz][0][jj];
            float dup = ((f0 == 1.0f) && (col0 == 0)) ? 0.f : 1.f;
            d_wfin[i] = w;
            d_wfin[4 + i] = w * dup;
        }
    }
}

// ---------------- kernel 5: weighted gather into out[2CN..3CN) -----------
__global__ void k_rtn(const float* __restrict__ G, const float* __restrict__ K,
                      const float* __restrict__ flag, float* __restrict__ out3) {
    __shared__ float w[8];
    int n = threadIdx.x;
    if (n < 8) w[n] = d_wfin[n];
    __syncthreads();
    float fl = flag[n];
    int ia = d_topI[0][n][0], ib = d_topI[0][n][1];
    int ic = d_topI[1][n][0], idd = d_topI[1][n][1];
    int cbase = blockIdx.x * 8;
    #pragma unroll
    for (int cc = 0; cc < 8; cc++) {
        int c = cbase + cc;
        const float* Kr = K + c * NN;
        const float* Gr = G + c * NN;
        float v = 0.f;
        if (fl == 1.0f)
            v = w[0] * Kr[ia] + w[1] * Kr[ib] + w[2] * Gr[ic] + w[3] * Gr[idd];
        if (n == 0)
            v += w[4] * Kr[0] + w[5] * Kr[0] + w[6] * Gr[0] + w[7] * Gr[0];
        out3[c * NN + n] = v;
    }
}

// ---------------- launch --------------------------------------------------
extern "C" void kernel_launch(void* const* d_in, const int* in_sizes, int n_in,
                              void* d_out, int out_size) {
    (void)in_sizes; (void)n_in; (void)out_size;
    const float* G = (const float*)d_in[0];   // generated (1,4096,32,32)
    const float* K = (const float*)d_in[1];   // known
    const float* M = (const float*)d_in[2];   // mask -> flag[1024]
    float* out = (float*)d_out;

    cudaFuncSetAttribute(k_gemm_mma, cudaFuncAttributeMaxDynamicSharedMemorySize, SMEM_GEMM);

    k_init<<<4, 256>>>();
    k_copynorm<<<dim3(4, 32), 256>>>(G, K, out);
    k_split<<<dim3(32, 128, 2), dim3(32, 8)>>>(G, K);
    k_gemm_mma<<<128, 256, SMEM_GEMM>>>(M);
    k_topk<<<2048, 256>>>(M);
    k_finalize<<<1, 256>>>(M);
    k_rtn<<<512, 1024>>>(G, K, M, out + (size_t)2 * CN);
}

// round 7
// speedup vs baseline: 1.2741x; 1.2741x over previous
#include <cuda_runtime.h>
#include <cuda_bf16.h>
#include <math.h>
#include <stdint.h>

#define CC 4096
#define NN 1024
#define CN (CC*NN)
#define KE 12288                 // expanded K = 3*CC (2-split, 3 cross products)
#define NEGV (-1e30f)

// ---------------- device scratch (no allocations allowed) ----------------
__device__ float d_D0[NN*NN];          // masked cos0 (vs known)
__device__ float d_D1[NN*NN];          // masked cos1 (vs generated)
__device__ float d_normG[NN];
__device__ float d_normK[NN];
__device__ float d_meanAcc[4];
__device__ int   d_topI[2][NN][2];
__device__ float d_wfin[8];
// expanded bf16 operands, [n][KE], packed as u32 (2 bf16)
__device__ uint32_t d_Ae [(size_t)NN*KE/2];   // G, A-pattern (b1,b1,b2)
__device__ uint32_t d_BeG[(size_t)NN*KE/2];   // G, B-pattern (b1,b2,b1)
__device__ uint32_t d_BeK[(size_t)NN*KE/2];   // K, B-pattern

// ---------------- helpers -------------------------------------------------
__device__ __forceinline__ uint32_t smem_u32(const void* p) {
    uint32_t a;
    asm("{ .reg .u64 t; cvta.to.shared.u64 t, %1; cvt.u32.u64 %0, t; }" : "=r"(a) : "l"(p));
    return a;
}
__device__ __forceinline__ unsigned short bfu(__nv_bfloat16 h) {
    unsigned short u; __builtin_memcpy(&u, &h, 2); return u;
}
__device__ __forceinline__ void cpa16(uint32_t dst, const void* src) {
    asm volatile("cp.async.cg.shared.global [%0], [%1], 16;" :: "r"(dst), "l"(src));
}
__device__ __forceinline__ void ldsm4(uint32_t* r, uint32_t addr) {
    asm volatile("ldmatrix.sync.aligned.m8n8.x4.shared.b16 {%0,%1,%2,%3}, [%4];"
                 : "=r"(r[0]), "=r"(r[1]), "=r"(r[2]), "=r"(r[3]) : "r"(addr));
}
__device__ __forceinline__ void mma16816(float* c, const uint32_t* a, const uint32_t* b) {
    asm volatile("mma.sync.aligned.m16n8k16.row.col.f32.bf16.bf16.f32 "
                 "{%0,%1,%2,%3}, {%4,%5,%6,%7}, {%8,%9}, {%0,%1,%2,%3};"
                 : "+f"(c[0]), "+f"(c[1]), "+f"(c[2]), "+f"(c[3])
                 : "r"(a[0]), "r"(a[1]), "r"(a[2]), "r"(a[3]), "r"(b[0]), "r"(b[1]));
}

// ---------------- kernel 0: zero accumulators ----------------------------
__global__ void k_init() {
    int t = blockIdx.x * blockDim.x + threadIdx.x;
    if (t < NN) { d_normG[t] = 0.f; d_normK[t] = 0.f; }
    if (t < 4)  d_meanAcc[t] = 0.f;
}

// ---------------- kernel 1: copy inputs to out[0..2CN) + column norms ----
__global__ void k_copynorm(const float* __restrict__ G, const float* __restrict__ K,
                           float* __restrict__ out) {
    int n  = blockIdx.x * 256 + threadIdx.x;
    int c0 = blockIdx.y * 128;
    float sg = 0.f, sk = 0.f;
    #pragma unroll 4
    for (int i = 0; i < 128; i++) {
        int idx = (c0 + i) * NN + n;
        float g = G[idx], k = K[idx];
        out[idx]      = g;
        out[CN + idx] = k;
        sg += g * g;
        sk += k * k;
    }
    atomicAdd(&d_normG[n], sg);
    atomicAdd(&d_normK[n], sk);
}

// ---------------- kernel 1b: transpose + 2-split + K-expansion -----------
// A-pattern per original k: (b1,b1,b2); B-pattern: (b1,b2,b1).
__global__ void k_split(const float* __restrict__ G, const float* __restrict__ K) {
    __shared__ float ts[32][33];
    int z = blockIdx.z;
    const float* src = z ? K : G;
    int n0 = blockIdx.x * 32, c0 = blockIdx.y * 32;
    int tx = threadIdx.x, ty = threadIdx.y;          // 32 x 8
    #pragma unroll
    for (int i = 0; i < 4; i++) {
        int cl = ty + i * 8;
        ts[cl][tx] = src[(size_t)(c0 + cl) * NN + n0 + tx];
    }
    __syncthreads();
    int tid = ty * 32 + tx;
    int nl = tid >> 3;                 // 0..31
    int cb = (tid & 7) * 4;            // 0..28
    size_t rb = ((size_t)(n0 + nl) * KE) >> 1;   // u32 row base
    #pragma unroll
    for (int p = 0; p < 2; p++) {
        int cl = cb + p * 2;                          // even
        float v0 = ts[cl][nl], v1 = ts[cl + 1][nl];
        __nv_bfloat16 h10 = __float2bfloat16_rn(v0);
        __nv_bfloat16 h20 = __float2bfloat16_rn(v0 - __bfloat162float(h10));
        __nv_bfloat16 h11 = __float2bfloat16_rn(v1);
        __nv_bfloat16 h21 = __float2bfloat16_rn(v1 - __bfloat162float(h11));
        uint32_t b10 = bfu(h10), b20 = bfu(h20), b11 = bfu(h11), b21 = bfu(h21);
        size_t o = rb + (size_t)(3 * (c0 + cl)) / 2;
        uint32_t wa0 = b10 | (b10 << 16);
        uint32_t wa1 = b20 | (b11 << 16);
        uint32_t wa2 = b11 | (b21 << 16);
        uint32_t wb0 = b10 | (b20 << 16);
        uint32_t wb1 = b10 | (b11 << 16);
        uint32_t wb2 = b21 | (b11 << 16);
        if (z == 0) {
            d_Ae[o] = wa0;  d_Ae[o + 1] = wa1;  d_Ae[o + 2] = wa2;
            d_BeG[o] = wb0; d_BeG[o + 1] = wb1; d_BeG[o + 2] = wb2;
        } else {
            d_BeK[o] = wb0; d_BeK[o + 1] = wb1; d_BeK[o + 2] = wb2;
        }
    }
}

// ---------------- kernel 2: bf16 mma.sync GEMM, 64x64 warp tiles, splitK2
#define KCHUNK 64
#define NKT    (KE / KCHUNK)          // 192
#define ROWB   144                    // 128B row + 16B pad (conflict-free ldmatrix)
#define TILEB  (128 * ROWB)           // 18432
#define STAGEB (2 * TILEB)            // 36864
#define NSTAGE 4
#define SMEM_GEMM (NSTAGE * STAGEB)   // 147456
#define REDSTRIDE 66                  // padded reduction row stride (floats)

__global__ __launch_bounds__(256)
void k_gemm_mma(const float* __restrict__ flag) {
    extern __shared__ char smem[];
    const uint32_t sb = smem_u32(smem);
    const int tid  = threadIdx.x;
    const int lane = tid & 31;
    const int w    = tid >> 5;
    const int wm   = ((w >> 1) & 1) * 64;   // warp m-origin (2x2 spatial grid)
    const int wn   = (w & 1) * 64;          // warp n-origin
    const int kw   = w >> 2;                // k-group: 0 -> ks{0,1}, 1 -> ks{2,3}

    const int bx = blockIdx.x;
    const int z  = bx >> 6;
    const int m0 = ((bx >> 3) & 7) * 128;
    const int n0 = (bx & 7) * 128;

    // COALESCED global->smem mapping: 8 consecutive threads cover one 128B
    // row-chunk; each warp-level cp.async touches 4 consecutive rows = 4 lines.
    const int lrow = tid >> 3;            // 0..31 (base row; +32 per rep)
    const int lc16 = tid & 7;             // 16B slot within the 128B row-chunk
    const __nv_bfloat16* gA = (const __nv_bfloat16*)d_Ae
        + (size_t)(m0 + lrow) * KE + lc16 * 8;
    const __nv_bfloat16* gB = (const __nv_bfloat16*)(z ? d_BeG : d_BeK)
        + (size_t)(n0 + lrow) * KE + lc16 * 8;
    const uint32_t sOfs = (uint32_t)(lrow * ROWB + lc16 * 16);

    #define ISSUE(kt, s) do {                                                    \
        uint32_t _d = sb + (uint32_t)(s) * STAGEB + sOfs;                        \
        const __nv_bfloat16* _a = gA + (size_t)(kt) * KCHUNK;                    \
        const __nv_bfloat16* _b = gB + (size_t)(kt) * KCHUNK;                    \
        cpa16(_d,                  _a);                                          \
        cpa16(_d + 32 * ROWB,      _a + (size_t)32 * KE);                        \
        cpa16(_d + 64 * ROWB,      _a + (size_t)64 * KE);                        \
        cpa16(_d + 96 * ROWB,      _a + (size_t)96 * KE);                        \
        cpa16(_d + TILEB,          _b);                                          \
        cpa16(_d + TILEB + 32*ROWB, _b + (size_t)32 * KE);                       \
        cpa16(_d + TILEB + 64*ROWB, _b + (size_t)64 * KE);                       \
        cpa16(_d + TILEB + 96*ROWB, _b + (size_t)96 * KE);                       \
    } while (0)

    float acc[4][8][4];
    #pragma unroll
    for (int i = 0; i < 4; i++)
        #pragma unroll
        for (int j = 0; j < 8; j++)
            #pragma unroll
            for (int q = 0; q < 4; q++) acc[i][j][q] = 0.f;

    // ldmatrix lane addresses (within a stage)
    const uint32_t aOff = (uint32_t)((wm + (lane & 7) + ((lane >> 3) & 1) * 8) * ROWB
                                     + ((lane >> 4) & 1) * 16);
    const uint32_t bOff = (uint32_t)TILEB
        + (uint32_t)((wn + (lane & 7) + ((lane >> 4) & 1) * 8) * ROWB
                     + ((lane >> 3) & 1) * 16);

    // prologue: 3 stages
    ISSUE(0, 0); asm volatile("cp.async.commit_group;" ::: "memory");
    ISSUE(1, 1); asm volatile("cp.async.commit_group;" ::: "memory");
    ISSUE(2, 2); asm volatile("cp.async.commit_group;" ::: "memory");

    for (int kt = 0; kt < NKT; kt++) {
        asm volatile("cp.async.wait_group 2;" ::: "memory");
        __syncthreads();
        int ip = kt + 3;
        if (ip < NKT) ISSUE(ip, ip & 3);
        asm volatile("cp.async.commit_group;" ::: "memory");

        const uint32_t stage = sb + (uint32_t)(kt & 3) * STAGEB;
        #pragma unroll
        for (int ksi = 0; ksi < 2; ksi++) {
            const int ks = kw * 2 + ksi;
            uint32_t fa[16], fb[16];
            #pragma unroll
            for (int i = 0; i < 4; i++)
                ldsm4(fa + i * 4, stage + aOff + i * (16 * ROWB) + ks * 32);
            #pragma unroll
            for (int j = 0; j < 4; j++)
                ldsm4(fb + j * 4, stage + bOff + j * (16 * ROWB) + ks * 32);
            #pragma unroll
            for (int i = 0; i < 4; i++)
                #pragma unroll
                for (int j = 0; j < 8; j++)
                    mma16816(acc[i][j], fa + i * 4, fb + (j >> 1) * 4 + (j & 1) * 2);
        }
    }
    asm volatile("cp.async.wait_group 0;" ::: "memory");
    __syncthreads();

    // ---- split-K reduction: warps 4-7 dump acc into padded smem ----
    float* red = (float*)smem;
    const int gid = lane >> 2, tig = lane & 3;
    const int t4 = w & 3;
    if (kw == 1) {
        float* base = red + t4 * (64 * REDSTRIDE);
        #pragma unroll
        for (int i = 0; i < 4; i++)
            #pragma unroll
            for (int half = 0; half < 2; half++) {
                int lr = i * 16 + gid + half * 8;
                float* dst = base + lr * REDSTRIDE;
                #pragma unroll
                for (int j = 0; j < 8; j++) {
                    int lc = j * 8 + tig * 2;
                    *(float2*)&dst[lc] =
                        make_float2(acc[i][j][half * 2], acc[i][j][half * 2 + 1]);
                }
            }
    }
    // norms/flags placed above the reduction area
    float* sNa = (float*)(smem + 4 * 64 * REDSTRIDE * 4);
    float* sNb = sNa + 128;
    float* sfl = sNb + 128;
    if (tid < 128) {
        sNa[tid] = d_normG[m0 + tid];
        sNb[tid] = (z ? d_normG : d_normK)[n0 + tid];
        sfl[tid] = flag[n0 + tid];
    }
    __syncthreads();

    // ---- warps 0-3: add partner partials, cosine + mask, write D ----
    if (kw == 0) {
        float* D = z ? d_D1 : d_D0;
        float* base = red + t4 * (64 * REDSTRIDE);
        #pragma unroll
        for (int i = 0; i < 4; i++)
            #pragma unroll
            for (int half = 0; half < 2; half++) {
                int lr = i * 16 + gid + half * 8;
                const float* src = base + lr * REDSTRIDE;
                float na = sNa[wm + lr];
                float* Drow = D + (size_t)(m0 + wm + lr) * NN + n0;
                #pragma unroll
                for (int j = 0; j < 8; j++) {
                    int lc = j * 8 + tig * 2;
                    int c = wn + lc;
                    float v0 = acc[i][j][half * 2 + 0] + src[lc];
                    float v1 = acc[i][j][half * 2 + 1] + src[lc + 1];
                    float f0 = sfl[c], f1 = sfl[c + 1];
                    bool k0 = z ? (f0 != 0.f) : (f0 == 0.f);
                    bool k1 = z ? (f1 != 0.f) : (f1 == 0.f);
                    float2 o;
                    o.x = k0 ? (v0 / sqrtf(na * sNb[c]))     : NEGV;
                    o.y = k1 ? (v1 / sqrtf(na * sNb[c + 1])) : NEGV;
                    *(float2*)&Drow[c] = o;
                }
            }
    }
    #undef ISSUE
}

// ---------------- kernel 3: top-2 per row (stable ties -> lower index) ---
__device__ __forceinline__ bool better(float va, int ia, float vb, int ib) {
    return (va > vb) || (va == vb && ia < ib);
}
__global__ void k_topk(const float* __restrict__ flag) {
    __shared__ float sv1[256], sv2[256];
    __shared__ int   si1[256], si2[256];
    int b = blockIdx.x;
    int z = b >> 10, row = b & 1023;
    const float* Dr = (z ? d_D1 : d_D0) + (size_t)row * NN;
    int tid = threadIdx.x;

    float v1 = -3.0e38f, v2 = -3.0e38f; int i1 = -1, i2 = -1;
    {
        int c = tid * 4;
        float4 v = *(const float4*)&Dr[c];
        float vv[4] = {v.x, v.y, v.z, v.w};
        #pragma unroll
        for (int j = 0; j < 4; j++) {
            if (better(vv[j], c + j, v1, i1)) { v2 = v1; i2 = i1; v1 = vv[j]; i1 = c + j; }
            else if (better(vv[j], c + j, v2, i2)) { v2 = vv[j]; i2 = c + j; }
        }
    }
    sv1[tid] = v1; si1[tid] = i1; sv2[tid] = v2; si2[tid] = i2;
    __syncthreads();
    for (int s = 128; s > 0; s >>= 1) {
        if (tid < s) {
            float w1 = sv1[tid + s], w2 = sv2[tid + s];
            int   j1 = si1[tid + s], j2 = si2[tid + s];
            float t1, t2; int ti1, ti2;
            if (better(v1, i1, w1, j1)) {
                t1 = v1; ti1 = i1;
                if (better(v2, i2, w1, j1)) { t2 = v2; ti2 = i2; }
                else                        { t2 = w1; ti2 = j1; }
            } else {
                t1 = w1; ti1 = j1;
                if (better(v1, i1, w2, j2)) { t2 = v1; ti2 = i1; }
                else                        { t2 = w2; ti2 = j2; }
            }
            v1 = t1; i1 = ti1; v2 = t2; i2 = ti2;
            sv1[tid] = v1; si1[tid] = i1; sv2[tid] = v2; si2[tid] = i2;
        }
        __syncthreads();
    }
    if (tid == 0) {
        d_topI[z][row][0] = i1; d_topI[z][row][1] = i2;
        if (flag[row] != 0.f) {
            atomicAdd(&d_meanAcc[z * 2 + 0], v1);
            atomicAdd(&d_meanAcc[z * 2 + 1], v2);
        }
    }
}

// ---------------- kernel 4: softmax weights + row-0 dup artifact ---------
__global__ void k_finalize(const float* __restrict__ flag) {
    __shared__ float sr[256];
    int tid = threadIdx.x;
    float s = 0.f;
    #pragma unroll
    for (int j = 0; j < 4; j++) s += flag[j * 256 + tid];
    sr[tid] = s; __syncthreads();
    for (int st = 128; st > 0; st >>= 1) {
        if (tid < st) sr[tid] += sr[tid + st];
        __syncthreads();
    }
    if (tid == 0) {
        float nm = sr[0];
        float means[4], mx = -3.0e38f;
        for (int i = 0; i < 4; i++) { means[i] = d_meanAcc[i] / nm; mx = fmaxf(mx, means[i]); }
        float e[4], Z = 0.f;
        for (int i = 0; i < 4; i++) { e[i] = expf(means[i] - mx); Z += e[i]; }
        float f0 = flag[0];
        for (int i = 0; i < 4; i++) {
            float w = e[i] / Z;
            int zz = i >> 1, jj = i & 1;
            int col0 = d_topI[zz][0][jj];
            float dup = ((f0 == 1.0f) && (col0 == 0)) ? 0.f : 1.f;
            d_wfin[i] = w;
            d_wfin[4 + i] = w * dup;
        }
    }
}

// ---------------- kernel 5: weighted gather into out[2CN..3CN) -----------
__global__ void k_rtn(const float* __restrict__ G, const float* __restrict__ K,
                      const float* __restrict__ flag, float* __restrict__ out3) {
    __shared__ float w[8];
    int n = threadIdx.x;
    if (n < 8) w[n] = d_wfin[n];
    __syncthreads();
    float fl = flag[n];
    int ia = d_topI[0][n][0], ib = d_topI[0][n][1];
    int ic = d_topI[1][n][0], idd = d_topI[1][n][1];
    int cbase = blockIdx.x * 8;
    #pragma unroll
    for (int cc = 0; cc < 8; cc++) {
        int c = cbase + cc;
        const float* Kr = K + c * NN;
        const float* Gr = G + c * NN;
        float v = 0.f;
        if (fl == 1.0f)
            v = w[0] * Kr[ia] + w[1] * Kr[ib] + w[2] * Gr[ic] + w[3] * Gr[idd];
        if (n == 0)
            v += w[4] * Kr[0] + w[5] * Kr[0] + w[6] * Gr[0] + w[7] * Gr[0];
        out3[c * NN + n] = v;
    }
}

// ---------------- launch --------------------------------------------------
extern "C" void kernel_launch(void* const* d_in, const int* in_sizes, int n_in,
                              void* d_out, int out_size) {
    (void)in_sizes; (void)n_in; (void)out_size;
    const float* G = (const float*)d_in[0];   // generated (1,4096,32,32)
    const float* K = (const float*)d_in[1];   // known
    const float* M = (const float*)d_in[2];   // mask -> flag[1024]
    float* out = (float*)d_out;

    cudaFuncSetAttribute(k_gemm_mma, cudaFuncAttributeMaxDynamicSharedMemorySize, SMEM_GEMM);

    k_init<<<4, 256>>>();
    k_copynorm<<<dim3(4, 32), 256>>>(G, K, out);
    k_split<<<dim3(32, 128, 2), dim3(32, 8)>>>(G, K);
    k_gemm_mma<<<128, 256, SMEM_GEMM>>>(M);
    k_topk<<<2048, 256>>>(M);
    k_finalize<<<1, 256>>>(M);
    k_rtn<<<512, 1024>>>(G, K, M, out + (size_t)2 * CN);
}

// round 8
// speedup vs baseline: 1.2831x; 1.0070x over previous
#include <cuda_runtime.h>
#include <cuda_bf16.h>
#include <math.h>
#include <stdint.h>

#define CC 4096
#define NN 1024
#define CN (CC*NN)
#define KE 12288                 // expanded K = 3*CC (2-split, 3 cross products)
#define NEGV (-1e30f)

// ---------------- device scratch (no allocations allowed) ----------------
__device__ float d_D0[NN*NN];          // masked cos0 (vs known)
__device__ float d_D1[NN*NN];          // masked cos1 (vs generated)
__device__ float d_normG[NN];
__device__ float d_normK[NN];
__device__ float d_meanAcc[4];
__device__ int   d_topI[2][NN][2];
__device__ float d_wfin[8];
// expanded bf16 operands, [n][KE], packed as u32 (2 bf16)
__device__ uint32_t d_Ae [(size_t)NN*KE/2];   // G, A-pattern (b1,b1,b2)
__device__ uint32_t d_BeG[(size_t)NN*KE/2];   // G, B-pattern (b1,b2,b1)
__device__ uint32_t d_BeK[(size_t)NN*KE/2];   // K, B-pattern

// ---------------- helpers -------------------------------------------------
__device__ __forceinline__ uint32_t smem_u32(const void* p) {
    uint32_t a;
    asm("{ .reg .u64 t; cvta.to.shared.u64 t, %1; cvt.u32.u64 %0, t; }" : "=r"(a) : "l"(p));
    return a;
}
__device__ __forceinline__ unsigned short bfu(__nv_bfloat16 h) {
    unsigned short u; __builtin_memcpy(&u, &h, 2); return u;
}
__device__ __forceinline__ void cpa16(uint32_t dst, const void* src) {
    asm volatile("cp.async.cg.shared.global [%0], [%1], 16;" :: "r"(dst), "l"(src));
}
__device__ __forceinline__ void ldsm4(uint32_t* r, uint32_t addr) {
    asm volatile("ldmatrix.sync.aligned.m8n8.x4.shared.b16 {%0,%1,%2,%3}, [%4];"
                 : "=r"(r[0]), "=r"(r[1]), "=r"(r[2]), "=r"(r[3]) : "r"(addr));
}
__device__ __forceinline__ void mma16816(float* c, const uint32_t* a, const uint32_t* b) {
    asm volatile("mma.sync.aligned.m16n8k16.row.col.f32.bf16.bf16.f32 "
                 "{%0,%1,%2,%3}, {%4,%5,%6,%7}, {%8,%9}, {%0,%1,%2,%3};"
                 : "+f"(c[0]), "+f"(c[1]), "+f"(c[2]), "+f"(c[3])
                 : "r"(a[0]), "r"(a[1]), "r"(a[2]), "r"(a[3]), "r"(b[0]), "r"(b[1]));
}

// ---------------- kernel 0: zero accumulators ----------------------------
__global__ void k_init() {
    int t = blockIdx.x * blockDim.x + threadIdx.x;
    if (t < NN) { d_normG[t] = 0.f; d_normK[t] = 0.f; }
    if (t < 4)  d_meanAcc[t] = 0.f;
}

// ---------------- kernel 1: copy inputs to out[0..2CN) + column norms ----
__global__ void k_copynorm(const float* __restrict__ G, const float* __restrict__ K,
                           float* __restrict__ out) {
    int n  = blockIdx.x * 256 + threadIdx.x;
    int c0 = blockIdx.y * 128;
    float sg = 0.f, sk = 0.f;
    #pragma unroll 4
    for (int i = 0; i < 128; i++) {
        int idx = (c0 + i) * NN + n;
        float g = G[idx], k = K[idx];
        out[idx]      = g;
        out[CN + idx] = k;
        sg += g * g;
        sk += k * k;
    }
    atomicAdd(&d_normG[n], sg);
    atomicAdd(&d_normK[n], sk);
}

// ---------------- kernel 1b: transpose + 2-split + K-expansion -----------
// A-pattern per original k: (b1,b1,b2); B-pattern: (b1,b2,b1).
__global__ void k_split(const float* __restrict__ G, const float* __restrict__ K) {
    __shared__ float ts[32][33];
    int z = blockIdx.z;
    const float* src = z ? K : G;
    int n0 = blockIdx.x * 32, c0 = blockIdx.y * 32;
    int tx = threadIdx.x, ty = threadIdx.y;          // 32 x 8
    #pragma unroll
    for (int i = 0; i < 4; i++) {
        int cl = ty + i * 8;
        ts[cl][tx] = src[(size_t)(c0 + cl) * NN + n0 + tx];
    }
    __syncthreads();
    int tid = ty * 32 + tx;
    int nl = tid >> 3;                 // 0..31
    int cb = (tid & 7) * 4;            // 0..28
    size_t rb = ((size_t)(n0 + nl) * KE) >> 1;   // u32 row base
    #pragma unroll
    for (int p = 0; p < 2; p++) {
        int cl = cb + p * 2;                          // even
        float v0 = ts[cl][nl], v1 = ts[cl + 1][nl];
        __nv_bfloat16 h10 = __float2bfloat16_rn(v0);
        __nv_bfloat16 h20 = __float2bfloat16_rn(v0 - __bfloat162float(h10));
        __nv_bfloat16 h11 = __float2bfloat16_rn(v1);
        __nv_bfloat16 h21 = __float2bfloat16_rn(v1 - __bfloat162float(h11));
        uint32_t b10 = bfu(h10), b20 = bfu(h20), b11 = bfu(h11), b21 = bfu(h21);
        size_t o = rb + (size_t)(3 * (c0 + cl)) / 2;
        uint32_t wa0 = b10 | (b10 << 16);
        uint32_t wa1 = b20 | (b11 << 16);
        uint32_t wa2 = b11 | (b21 << 16);
        uint32_t wb0 = b10 | (b20 << 16);
        uint32_t wb1 = b10 | (b11 << 16);
        uint32_t wb2 = b21 | (b11 << 16);
        if (z == 0) {
            d_Ae[o] = wa0;  d_Ae[o + 1] = wa1;  d_Ae[o + 2] = wa2;
            d_BeG[o] = wb0; d_BeG[o + 1] = wb1; d_BeG[o + 2] = wb2;
        } else {
            d_BeK[o] = wb0; d_BeK[o + 1] = wb1; d_BeK[o + 2] = wb2;
        }
    }
}

// ---------------- kernel 2: bf16 mma.sync GEMM ---------------------------
// 512 threads: 16 warps = 2x4 spatial grid (64x32 warp tiles) x split-K2.
#define KCHUNK 64
#define NKT    (KE / KCHUNK)          // 192
#define ROWB   144                    // 128B row + 16B pad (conflict-free ldmatrix)
#define TILEB  (128 * ROWB)           // 18432
#define STAGEB (2 * TILEB)            // 36864
#define NSTAGE 4
#define SMEM_GEMM (NSTAGE * STAGEB)   // 147456
#define REDSTRIDE 34                  // padded reduction row stride (floats, even)

__global__ __launch_bounds__(512)
void k_gemm_mma(const float* __restrict__ flag) {
    extern __shared__ char smem[];
    const uint32_t sb = smem_u32(smem);
    const int tid  = threadIdx.x;
    const int lane = tid & 31;
    const int w    = tid >> 5;          // 0..15
    const int ws   = w & 7;             // spatial slot
    const int kw   = w >> 3;            // k-group: 0 -> ks{0,1}, 1 -> ks{2,3}
    const int wm   = (ws >> 2) * 64;    // warp m-origin
    const int wn   = (ws & 3) * 32;     // warp n-origin

    const int bx = blockIdx.x;
    const int z  = bx >> 6;
    const int m0 = ((bx >> 3) & 7) * 128;
    const int n0 = (bx & 7) * 128;

    // COALESCED global->smem mapping: 8 consecutive threads cover one 128B
    // row-chunk; each thread loads rows lrow and lrow+64 of A and B.
    const int lrow = tid >> 3;            // 0..63
    const int lc16 = tid & 7;             // 16B slot within the 128B row-chunk
    const __nv_bfloat16* gA = (const __nv_bfloat16*)d_Ae
        + (size_t)(m0 + lrow) * KE + lc16 * 8;
    const __nv_bfloat16* gB = (const __nv_bfloat16*)(z ? d_BeG : d_BeK)
        + (size_t)(n0 + lrow) * KE + lc16 * 8;
    const uint32_t sOfs = (uint32_t)(lrow * ROWB + lc16 * 16);

    #define ISSUE(kt, s) do {                                                    \
        uint32_t _d = sb + (uint32_t)(s) * STAGEB + sOfs;                        \
        const __nv_bfloat16* _a = gA + (size_t)(kt) * KCHUNK;                    \
        const __nv_bfloat16* _b = gB + (size_t)(kt) * KCHUNK;                    \
        cpa16(_d,                   _a);                                         \
        cpa16(_d + 64 * ROWB,       _a + (size_t)64 * KE);                       \
        cpa16(_d + TILEB,           _b);                                         \
        cpa16(_d + TILEB + 64*ROWB, _b + (size_t)64 * KE);                       \
    } while (0)

    float acc[4][4][4];
    #pragma unroll
    for (int i = 0; i < 4; i++)
        #pragma unroll
        for (int j = 0; j < 4; j++)
            #pragma unroll
            for (int q = 0; q < 4; q++) acc[i][j][q] = 0.f;

    // ldmatrix lane addresses (within a stage)
    const uint32_t aOff = (uint32_t)((wm + (lane & 7) + ((lane >> 3) & 1) * 8) * ROWB
                                     + ((lane >> 4) & 1) * 16);
    const uint32_t bOff = (uint32_t)TILEB
        + (uint32_t)((wn + (lane & 7) + ((lane >> 4) & 1) * 8) * ROWB
                     + ((lane >> 3) & 1) * 16);

    // prologue: 3 stages
    ISSUE(0, 0); asm volatile("cp.async.commit_group;" ::: "memory");
    ISSUE(1, 1); asm volatile("cp.async.commit_group;" ::: "memory");
    ISSUE(2, 2); asm volatile("cp.async.commit_group;" ::: "memory");

    for (int kt = 0; kt < NKT; kt++) {
        asm volatile("cp.async.wait_group 2;" ::: "memory");
        __syncthreads();
        int ip = kt + 3;
        if (ip < NKT) ISSUE(ip, ip & 3);
        asm volatile("cp.async.commit_group;" ::: "memory");

        const uint32_t stage = sb + (uint32_t)(kt & 3) * STAGEB;
        #pragma unroll
        for (int ksi = 0; ksi < 2; ksi++) {
            const int ks = kw * 2 + ksi;
            uint32_t fa[16], fb[8];
            #pragma unroll
            for (int i = 0; i < 4; i++)
                ldsm4(fa + i * 4, stage + aOff + i * (16 * ROWB) + ks * 32);
            #pragma unroll
            for (int j = 0; j < 2; j++)
                ldsm4(fb + j * 4, stage + bOff + j * (16 * ROWB) + ks * 32);
            #pragma unroll
            for (int i = 0; i < 4; i++)
                #pragma unroll
                for (int j = 0; j < 4; j++)
                    mma16816(acc[i][j], fa + i * 4, fb + j * 2);
        }
    }
    asm volatile("cp.async.wait_group 0;" ::: "memory");
    __syncthreads();

    // ---- split-K reduction: k-group-1 warps dump acc into padded smem ----
    float* red = (float*)smem;
    const int gid = lane >> 2, tig = lane & 3;
    if (kw == 1) {
        float* base = red + ws * (64 * REDSTRIDE);
        #pragma unroll
        for (int i = 0; i < 4; i++)
            #pragma unroll
            for (int half = 0; half < 2; half++) {
                int lr = i * 16 + gid + half * 8;
                float* dst = base + lr * REDSTRIDE;
                #pragma unroll
                for (int j = 0; j < 4; j++) {
                    int lc = j * 8 + tig * 2;
                    *(float2*)&dst[lc] =
                        make_float2(acc[i][j][half * 2], acc[i][j][half * 2 + 1]);
                }
            }
    }
    // norms/flags placed above the reduction area
    float* sNa = (float*)(smem + 8 * 64 * REDSTRIDE * 4);
    float* sNb = sNa + 128;
    float* sfl = sNb + 128;
    if (tid < 128) {
        sNa[tid] = d_normG[m0 + tid];
        sNb[tid] = (z ? d_normG : d_normK)[n0 + tid];
        sfl[tid] = flag[n0 + tid];
    }
    __syncthreads();

    // ---- k-group-0 warps: add partner partials, cosine + mask, write D ----
    if (kw == 0) {
        float* D = z ? d_D1 : d_D0;
        float* base = red + ws * (64 * REDSTRIDE);
        #pragma unroll
        for (int i = 0; i < 4; i++)
            #pragma unroll
            for (int half = 0; half < 2; half++) {
                int lr = i * 16 + gid + half * 8;
                const float* src = base + lr * REDSTRIDE;
                float na = sNa[wm + lr];
                float* Drow = D + (size_t)(m0 + wm + lr) * NN + n0;
                #pragma unroll
                for (int j = 0; j < 4; j++) {
                    int lc = j * 8 + tig * 2;
                    int c = wn + lc;
                    float v0 = acc[i][j][half * 2 + 0] + src[lc];
                    float v1 = acc[i][j][half * 2 + 1] + src[lc + 1];
                    float f0 = sfl[c], f1 = sfl[c + 1];
                    bool k0 = z ? (f0 != 0.f) : (f0 == 0.f);
                    bool k1 = z ? (f1 != 0.f) : (f1 == 0.f);
                    float2 o;
                    o.x = k0 ? (v0 / sqrtf(na * sNb[c]))     : NEGV;
                    o.y = k1 ? (v1 / sqrtf(na * sNb[c + 1])) : NEGV;
                    *(float2*)&Drow[c] = o;
                }
            }
    }
    #undef ISSUE
}

// ---------------- kernel 3: top-2 per row (stable ties -> lower index) ---
__device__ __forceinline__ bool better(float va, int ia, float vb, int ib) {
    return (va > vb) || (va == vb && ia < ib);
}
__global__ void k_topk(const float* __restrict__ flag) {
    __shared__ float sv1[256], sv2[256];
    __shared__ int   si1[256], si2[256];
    int b = blockIdx.x;
    int z = b >> 10, row = b & 1023;
    const float* Dr = (z ? d_D1 : d_D0) + (size_t)row * NN;
    int tid = threadIdx.x;

    float v1 = -3.0e38f, v2 = -3.0e38f; int i1 = -1, i2 = -1;
    {
        int c = tid * 4;
        float4 v = *(const float4*)&Dr[c];
        float vv[4] = {v.x, v.y, v.z, v.w};
        #pragma unroll
        for (int j = 0; j < 4; j++) {
            if (better(vv[j], c + j, v1, i1)) { v2 = v1; i2 = i1; v1 = vv[j]; i1 = c + j; }
            else if (better(vv[j], c + j, v2, i2)) { v2 = vv[j]; i2 = c + j; }
        }
    }
    sv1[tid] = v1; si1[tid] = i1; sv2[tid] = v2; si2[tid] = i2;
    __syncthreads();
    for (int s = 128; s > 0; s >>= 1) {
        if (tid < s) {
            float w1 = sv1[tid + s], w2 = sv2[tid + s];
            int   j1 = si1[tid + s], j2 = si2[tid + s];
            float t1, t2; int ti1, ti2;
            if (better(v1, i1, w1, j1)) {
                t1 = v1; ti1 = i1;
                if (better(v2, i2, w1, j1)) { t2 = v2; ti2 = i2; }
                else                        { t2 = w1; ti2 = j1; }
            } else {
                t1 = w1; ti1 = j1;
                if (better(v1, i1, w2, j2)) { t2 = v1; ti2 = i1; }
                else                        { t2 = w2; ti2 = j2; }
            }
            v1 = t1; i1 = ti1; v2 = t2; i2 = ti2;
            sv1[tid] = v1; si1[tid] = i1; sv2[tid] = v2; si2[tid] = i2;
        }
        __syncthreads();
    }
    if (tid == 0) {
        d_topI[z][row][0] = i1; d_topI[z][row][1] = i2;
        if (flag[row] != 0.f) {
            atomicAdd(&d_meanAcc[z * 2 + 0], v1);
            atomicAdd(&d_meanAcc[z * 2 + 1], v2);
        }
    }
}

// ---------------- kernel 4: softmax weights + row-0 dup artifact ---------
__global__ void k_finalize(const float* __restrict__ flag) {
    __shared__ float sr[256];
    int tid = threadIdx.x;
    float s = 0.f;
    #pragma unroll
    for (int j = 0; j < 4; j++) s += flag[j * 256 + tid];
    sr[tid] = s; __syncthreads();
    for (int st = 128; st > 0; st >>= 1) {
        if (tid < st) sr[tid] += sr[tid + st];
        __syncthreads();
    }
    if (tid == 0) {
        float nm = sr[0];
        float means[4], mx = -3.0e38f;
        for (int i = 0; i < 4; i++) { means[i] = d_meanAcc[i] / nm; mx = fmaxf(mx, means[i]); }
        float e[4], Z = 0.f;
        for (int i = 0; i < 4; i++) { e[i] = expf(means[i] - mx); Z += e[i]; }
        float f0 = flag[0];
        for (int i = 0; i < 4; i++) {
            float w = e[i] / Z;
            int zz = i >> 1, jj = i & 1;
            int col0 = d_topI[zz][0][jj];
            float dup = ((f0 == 1.0f) && (col0 == 0)) ? 0.f : 1.f;
            d_wfin[i] = w;
            d_wfin[4 + i] = w * dup;
        }
    }
}

// ---------------- kernel 5: weighted gather into out[2CN..3CN) -----------
__global__ void k_rtn(const float* __restrict__ G, const float* __restrict__ K,
                      const float* __restrict__ flag, float* __restrict__ out3) {
    __shared__ float w[8];
    int n = threadIdx.x;
    if (n < 8) w[n] = d_wfin[n];
    __syncthreads();
    float fl = flag[n];
    int ia = d_topI[0][n][0], ib = d_topI[0][n][1];
    int ic = d_topI[1][n][0], idd = d_topI[1][n][1];
    int cbase = blockIdx.x * 8;
    #pragma unroll
    for (int cc = 0; cc < 8; cc++) {
        int c = cbase + cc;
        const float* Kr = K + c * NN;
        const float* Gr = G + c * NN;
        float v = 0.f;
        if (fl == 1.0f)
            v = w[0] * Kr[ia] + w[1] * Kr[ib] + w[2] * Gr[ic] + w[3] * Gr[idd];
        if (n == 0)
            v += w[4] * Kr[0] + w[5] * Kr[0] + w[6] * Gr[0] + w[7] * Gr[0];
        out3[c * NN + n] = v;
    }
}

// ---------------- launch --------------------------------------------------
extern "C" void kernel_launch(void* const* d_in, const int* in_sizes, int n_in,
                              void* d_out, int out_size) {
    (void)in_sizes; (void)n_in; (void)out_size;
    const float* G = (const float*)d_in[0];   // generated (1,4096,32,32)
    const float* K = (const float*)d_in[1];   // known
    const float* M = (const float*)d_in[2];   // mask -> flag[1024]
    float* out = (float*)d_out;

    cudaFuncSetAttribute(k_gemm_mma, cudaFuncAttributeMaxDynamicSharedMemorySize, SMEM_GEMM);

    k_init<<<4, 256>>>();
    k_copynorm<<<dim3(4, 32), 256>>>(G, K, out);
    k_split<<<dim3(32, 128, 2), dim3(32, 8)>>>(G, K);
    k_gemm_mma<<<128, 512, SMEM_GEMM>>>(M);
    k_topk<<<2048, 256>>>(M);
    k_finalize<<<1, 256>>>(M);
    k_rtn<<<512, 1024>>>(G, K, M, out + (size_t)2 * CN);
}

// round 9
// speedup vs baseline: 1.6867x; 1.3146x over previous
#include <cuda_runtime.h>
#include <cuda_bf16.h>
#include <math.h>
#include <stdint.h>

#define CC 4096
#define NN 1024
#define CN (CC*NN)
#define NEGV (-1e30f)

// ---------------- device scratch (no allocations allowed) ----------------
__device__ float d_D0[NN*NN];          // masked cos0 (vs known)
__device__ float d_D1[NN*NN];          // masked cos1 (vs generated)
__device__ float d_normG[NN];
__device__ float d_normK[NN];
__device__ float d_meanAcc[4];
__device__ int   d_topI[2][NN][2];
__device__ float d_wfin[8];
// bf16 2-split, transposed [n][c]; index 0 = G, 1 = K
__device__ __nv_bfloat16 d_S1[2][(size_t)NN*CC];
__device__ __nv_bfloat16 d_S2[2][(size_t)NN*CC];

// ---------------- helpers -------------------------------------------------
__device__ __forceinline__ uint32_t smem_u32(const void* p) {
    uint32_t a;
    asm("{ .reg .u64 t; cvta.to.shared.u64 t, %1; cvt.u32.u64 %0, t; }" : "=r"(a) : "l"(p));
    return a;
}
__device__ __forceinline__ void cpa16(uint32_t dst, const void* src) {
    asm volatile("cp.async.cg.shared.global [%0], [%1], 16;" :: "r"(dst), "l"(src));
}
__device__ __forceinline__ void ldsm4(uint32_t* r, uint32_t addr) {
    asm volatile("ldmatrix.sync.aligned.m8n8.x4.shared.b16 {%0,%1,%2,%3}, [%4];"
                 : "=r"(r[0]), "=r"(r[1]), "=r"(r[2]), "=r"(r[3]) : "r"(addr));
}
__device__ __forceinline__ void mma16816(float* c, const uint32_t* a, const uint32_t* b) {
    asm volatile("mma.sync.aligned.m16n8k16.row.col.f32.bf16.bf16.f32 "
                 "{%0,%1,%2,%3}, {%4,%5,%6,%7}, {%8,%9}, {%0,%1,%2,%3};"
                 : "+f"(c[0]), "+f"(c[1]), "+f"(c[2]), "+f"(c[3])
                 : "r"(a[0]), "r"(a[1]), "r"(a[2]), "r"(a[3]), "r"(b[0]), "r"(b[1]));
}

// ---------------- kernel 0: zero accumulators ----------------------------
__global__ void k_init() {
    int t = blockIdx.x * blockDim.x + threadIdx.x;
    if (t < NN) { d_normG[t] = 0.f; d_normK[t] = 0.f; }
    if (t < 4)  d_meanAcc[t] = 0.f;
}

// ---------------- kernel 1: fused copy + norms + transpose + 2-split -----
__global__ void k_prep(const float* __restrict__ G, const float* __restrict__ Kn,
                       float* __restrict__ out) {
    __shared__ float ts[32][33];
    int z = blockIdx.z;
    const float* src = z ? Kn : G;
    float* dst = out + (size_t)z * CN;
    int n0 = blockIdx.x * 32, c0 = blockIdx.y * 32;
    int tx = threadIdx.x, ty = threadIdx.y;          // 32 x 8
    #pragma unroll
    for (int i = 0; i < 4; i++) {
        int cl = ty + i * 8;
        size_t idx = (size_t)(c0 + cl) * NN + n0 + tx;
        float v = src[idx];
        dst[idx] = v;
        ts[cl][tx] = v;
    }
    __syncthreads();
    float* nrm = z ? d_normK : d_normG;
    __nv_bfloat16* S1 = d_S1[z];
    __nv_bfloat16* S2 = d_S2[z];
    #pragma unroll
    for (int i = 0; i < 4; i++) {
        int nl = ty + i * 8;                         // warp = ty; lanes = tx = c
        float v = ts[tx][nl];                        // element (c0+tx, n0+nl)
        float sq = v * v;
        #pragma unroll
        for (int off = 16; off; off >>= 1) sq += __shfl_down_sync(0xffffffffu, sq, off);
        if (tx == 0) atomicAdd(&nrm[n0 + nl], sq);
        __nv_bfloat16 h1 = __float2bfloat16_rn(v);
        float r = v - __bfloat162float(h1);
        __nv_bfloat16 h2 = __float2bfloat16_rn(r);
        size_t o = (size_t)(n0 + nl) * CC + c0 + tx;
        S1[o] = h1; S2[o] = h2;
    }
}

// ---------------- kernel 2: bf16 mma.sync GEMM ---------------------------
// 512 threads, 16 warps = 2x4 spatial (64x32 tiles) x split-K2.
// Per K-chunk (64 cols): tiles A1,A2,B1,B2 in smem; products A1B1+A1B2+A2B1.
// z=1 (G.G^T): only upper-tri tiles; mirror via smem transpose.
#define KCHUNK 64
#define NCHK   (CC / KCHUNK)          // 64
#define ROWB   144                    // 128B row + 16B pad
#define TILEB  (128 * ROWB)           // 18432
#define STAGEB (4 * TILEB)            // 73728 (A1,A2,B1,B2)
#define SMEM_GEMM (2 * STAGEB + 2048) // 149504
#define NORMOFF (2 * STAGEB)
#define REDSTRIDE 34
#define TBOFF  STAGEB                 // transpose buffer at 73728 (above red area)
#define TS     129

__global__ __launch_bounds__(512)
void k_gemm_mma(const float* __restrict__ flag) {
    extern __shared__ char smem[];
    const uint32_t sb = smem_u32(smem);
    const int tid  = threadIdx.x;
    const int lane = tid & 31;
    const int w    = tid >> 5;          // 0..15
    const int ws   = w & 7;             // spatial slot
    const int kw   = w >> 3;            // k-group
    const int wm   = (ws >> 2) * 64;
    const int wn   = (ws & 3) * 32;

    // tile decode: bx<64 -> z=0 full grid; else z=1 upper triangle
    const int bx = blockIdx.x;
    int z, mi, nj;
    if (bx < 64) { z = 0; mi = bx >> 3; nj = bx & 7; }
    else {
        z = 1; int t = bx - 64; mi = 0;
        while (t >= 8 - mi) { t -= 8 - mi; mi++; }
        nj = mi + t;
    }
    const int m0 = mi * 128, n0 = nj * 128;
    const bool mirror = (z == 1) && (mi != nj);

    const int zb = (z == 1) ? 0 : 1;    // B source: z0 -> K, z1 -> G
    const int lrow = tid >> 3;          // 0..63
    const int lc16 = tid & 7;
    const __nv_bfloat16* gA1 = d_S1[0]  + (size_t)(m0 + lrow) * CC + lc16 * 8;
    const __nv_bfloat16* gA2 = d_S2[0]  + (size_t)(m0 + lrow) * CC + lc16 * 8;
    const __nv_bfloat16* gB1 = d_S1[zb] + (size_t)(n0 + lrow) * CC + lc16 * 8;
    const __nv_bfloat16* gB2 = d_S2[zb] + (size_t)(n0 + lrow) * CC + lc16 * 8;
    const uint32_t sOfs = (uint32_t)(lrow * ROWB + lc16 * 16);

    #define ISSUE(kt, s) do {                                                    \
        uint32_t _d = sb + (uint32_t)(s) * STAGEB + sOfs;                        \
        size_t _ko = (size_t)(kt) * KCHUNK;                                      \
        cpa16(_d,                       gA1 + _ko);                              \
        cpa16(_d + 64 * ROWB,           gA1 + _ko + (size_t)64 * CC);            \
        cpa16(_d + TILEB,               gA2 + _ko);                              \
        cpa16(_d + TILEB + 64 * ROWB,   gA2 + _ko + (size_t)64 * CC);            \
        cpa16(_d + 2 * TILEB,           gB1 + _ko);                              \
        cpa16(_d + 2 * TILEB + 64*ROWB, gB1 + _ko + (size_t)64 * CC);            \
        cpa16(_d + 3 * TILEB,           gB2 + _ko);                              \
        cpa16(_d + 3 * TILEB + 64*ROWB, gB2 + _ko + (size_t)64 * CC);            \
    } while (0)

    float acc[4][4][4];
    #pragma unroll
    for (int i = 0; i < 4; i++)
        #pragma unroll
        for (int j = 0; j < 4; j++)
            #pragma unroll
            for (int q = 0; q < 4; q++) acc[i][j][q] = 0.f;

    const uint32_t aOff = (uint32_t)((wm + (lane & 7) + ((lane >> 3) & 1) * 8) * ROWB
                                     + ((lane >> 4) & 1) * 16);
    const uint32_t bOff = (uint32_t)((wn + (lane & 7) + ((lane >> 4) & 1) * 8) * ROWB
                                     + ((lane >> 3) & 1) * 16);

    ISSUE(0, 0); asm volatile("cp.async.commit_group;" ::: "memory");
    ISSUE(1, 1); asm volatile("cp.async.commit_group;" ::: "memory");

    for (int kt = 0; kt < NCHK; kt++) {
        asm volatile("cp.async.wait_group 1;" ::: "memory");
        __syncthreads();
        const uint32_t stage = sb + (uint32_t)(kt & 1) * STAGEB;
        #pragma unroll
        for (int ksi = 0; ksi < 2; ksi++) {
            const int ks = kw * 2 + ksi;
            uint32_t fa[16], fb1[8], fb2[8];
            #pragma unroll
            for (int i = 0; i < 4; i++)
                ldsm4(fa + i * 4, stage + aOff + i * (16 * ROWB) + ks * 32);
            #pragma unroll
            for (int j = 0; j < 2; j++) {
                ldsm4(fb1 + j * 4, stage + 2 * TILEB + bOff + j * (16 * ROWB) + ks * 32);
                ldsm4(fb2 + j * 4, stage + 3 * TILEB + bOff + j * (16 * ROWB) + ks * 32);
            }
            #pragma unroll
            for (int i = 0; i < 4; i++)
                #pragma unroll
                for (int j = 0; j < 4; j++) {
                    mma16816(acc[i][j], fa + i * 4, fb1 + j * 2);
                    mma16816(acc[i][j], fa + i * 4, fb2 + j * 2);
                }
            #pragma unroll
            for (int i = 0; i < 4; i++)
                ldsm4(fa + i * 4, stage + TILEB + aOff + i * (16 * ROWB) + ks * 32);
            #pragma unroll
            for (int i = 0; i < 4; i++)
                #pragma unroll
                for (int j = 0; j < 4; j++)
                    mma16816(acc[i][j], fa + i * 4, fb1 + j * 2);
        }
        __syncthreads();
        if (kt + 2 < NCHK) ISSUE(kt + 2, kt & 1);
        asm volatile("cp.async.commit_group;" ::: "memory");
    }
    asm volatile("cp.async.wait_group 0;" ::: "memory");
    __syncthreads();

    // ---- split-K: kw1 dumps partials; also load norms/flags ----
    float* red  = (float*)smem;
    float* Tbuf = (float*)(smem + TBOFF);
    float* sNa  = (float*)(smem + NORMOFF);
    float* sNb  = sNa + 128;
    float* sflN = sNb + 128;
    float* sflM = sflN + 128;
    const int gid = lane >> 2, tig = lane & 3;
    if (kw == 1) {
        float* base = red + ws * (64 * REDSTRIDE);
        #pragma unroll
        for (int i = 0; i < 4; i++)
            #pragma unroll
            for (int half = 0; half < 2; half++) {
                int lr = i * 16 + gid + half * 8;
                float* dst = base + lr * REDSTRIDE;
                #pragma unroll
                for (int j = 0; j < 4; j++) {
                    int lc = j * 8 + tig * 2;
                    *(float2*)&dst[lc] =
                        make_float2(acc[i][j][half * 2], acc[i][j][half * 2 + 1]);
                }
            }
    }
    if (tid < 128) {
        sNa[tid]  = d_normG[m0 + tid];
        sNb[tid]  = (z ? d_normG : d_normK)[n0 + tid];
        sflN[tid] = flag[n0 + tid];
        sflM[tid] = flag[m0 + tid];
    }
    __syncthreads();

    // ---- kw0: sum, cosine, direct masked write (+ stash for mirror) ----
    if (kw == 0) {
        float* D = z ? d_D1 : d_D0;
        float* base = red + ws * (64 * REDSTRIDE);
        #pragma unroll
        for (int i = 0; i < 4; i++)
            #pragma unroll
            for (int half = 0; half < 2; half++) {
                int lr = i * 16 + gid + half * 8;
                const float* src = base + lr * REDSTRIDE;
                float na = sNa[wm + lr];
                float* Drow = D + (size_t)(m0 + wm + lr) * NN + n0;
                #pragma unroll
                for (int j = 0; j < 4; j++) {
                    int lc = j * 8 + tig * 2;
                    int c = wn + lc;
                    float v0 = acc[i][j][half * 2 + 0] + src[lc];
                    float v1 = acc[i][j][half * 2 + 1] + src[lc + 1];
                    float r0 = v0 / sqrtf(na * sNb[c]);
                    float r1 = v1 / sqrtf(na * sNb[c + 1]);
                    float f0 = sflN[c], f1 = sflN[c + 1];
                    bool k0 = z ? (f0 != 0.f) : (f0 == 0.f);
                    bool k1 = z ? (f1 != 0.f) : (f1 == 0.f);
                    float2 o;
                    o.x = k0 ? r0 : NEGV;
                    o.y = k1 ? r1 : NEGV;
                    *(float2*)&Drow[c] = o;
                    if (mirror) {
                        Tbuf[(size_t)c * TS + wm + lr]       = r0;
                        Tbuf[(size_t)(c + 1) * TS + wm + lr] = r1;
                    }
                }
            }
    }

    // ---- mirror write: D1[n-block][m-block], col-mask flag[m] ----
    if (mirror) {
        __syncthreads();
        int rowc = tid >> 2;               // 0..127 (column index c, now a row)
        int cg   = (tid & 3) * 32;
        const float* tb = Tbuf + (size_t)rowc * TS + cg;
        float* Drow = d_D1 + (size_t)(n0 + rowc) * NN + m0 + cg;
        #pragma unroll
        for (int q = 0; q < 32; q += 4) {
            float4 o;
            o.x = (sflM[cg + q + 0] != 0.f) ? tb[q + 0] : NEGV;
            o.y = (sflM[cg + q + 1] != 0.f) ? tb[q + 1] : NEGV;
            o.z = (sflM[cg + q + 2] != 0.f) ? tb[q + 2] : NEGV;
            o.w = (sflM[cg + q + 3] != 0.f) ? tb[q + 3] : NEGV;
            *(float4*)&Drow[q] = o;
        }
    }
    #undef ISSUE
}

// ---------------- kernel 3: top-2 per row (stable ties -> lower index) ---
__device__ __forceinline__ bool better(float va, int ia, float vb, int ib) {
    return (va > vb) || (va == vb && ia < ib);
}
__global__ void k_topk(const float* __restrict__ flag) {
    __shared__ float sv1[256], sv2[256];
    __shared__ int   si1[256], si2[256];
    int b = blockIdx.x;
    int z = b >> 10, row = b & 1023;
    const float* Dr = (z ? d_D1 : d_D0) + (size_t)row * NN;
    int tid = threadIdx.x;

    float v1 = -3.0e38f, v2 = -3.0e38f; int i1 = -1, i2 = -1;
    {
        int c = tid * 4;
        float4 v = *(const float4*)&Dr[c];
        float vv[4] = {v.x, v.y, v.z, v.w};
        #pragma unroll
        for (int j = 0; j < 4; j++) {
            if (better(vv[j], c + j, v1, i1)) { v2 = v1; i2 = i1; v1 = vv[j]; i1 = c + j; }
            else if (better(vv[j], c + j, v2, i2)) { v2 = vv[j]; i2 = c + j; }
        }
    }
    sv1[tid] = v1; si1[tid] = i1; sv2[tid] = v2; si2[tid] = i2;
    __syncthreads();
    for (int s = 128; s > 0; s >>= 1) {
        if (tid < s) {
            float w1 = sv1[tid + s], w2 = sv2[tid + s];
            int   j1 = si1[tid + s], j2 = si2[tid + s];
            float t1, t2; int ti1, ti2;
            if (better(v1, i1, w1, j1)) {
                t1 = v1; ti1 = i1;
                if (better(v2, i2, w1, j1)) { t2 = v2; ti2 = i2; }
                else                        { t2 = w1; ti2 = j1; }
            } else {
                t1 = w1; ti1 = j1;
                if (better(v1, i1, w2, j2)) { t2 = v1; ti2 = i1; }
                else                        { t2 = w2; ti2 = j2; }
            }
            v1 = t1; i1 = ti1; v2 = t2; i2 = ti2;
            sv1[tid] = v1; si1[tid] = i1; sv2[tid] = v2; si2[tid] = i2;
        }
        __syncthreads();
    }
    if (tid == 0) {
        d_topI[z][row][0] = i1; d_topI[z][row][1] = i2;
        if (flag[row] != 0.f) {
            atomicAdd(&d_meanAcc[z * 2 + 0], v1);
            atomicAdd(&d_meanAcc[z * 2 + 1], v2);
        }
    }
}

// ---------------- kernel 4: softmax weights + row-0 dup artifact ---------
__global__ void k_finalize(const float* __restrict__ flag) {
    __shared__ float sr[256];
    int tid = threadIdx.x;
    float s = 0.f;
    #pragma unroll
    for (int j = 0; j < 4; j++) s += flag[j * 256 + tid];
    sr[tid] = s; __syncthreads();
    for (int st = 128; st > 0; st >>= 1) {
        if (tid < st) sr[tid] += sr[tid + st];
        __syncthreads();
    }
    if (tid == 0) {
        float nm = sr[0];
        float means[4], mx = -3.0e38f;
        for (int i = 0; i < 4; i++) { means[i] = d_meanAcc[i] / nm; mx = fmaxf(mx, means[i]); }
        float e[4], Z = 0.f;
        for (int i = 0; i < 4; i++) { e[i] = expf(means[i] - mx); Z += e[i]; }
        float f0 = flag[0];
        for (int i = 0; i < 4; i++) {
            float w = e[i] / Z;
            int zz = i >> 1, jj = i & 1;
            int col0 = d_topI[zz][0][jj];
            float dup = ((f0 == 1.0f) && (col0 == 0)) ? 0.f : 1.f;
            d_wfin[i] = w;
            d_wfin[4 + i] = w * dup;
        }
    }
}

// ---------------- kernel 5: weighted gather into out[2CN..3CN) -----------
__global__ void k_rtn(const float* __restrict__ G, const float* __restrict__ K,
                      const float* __restrict__ flag, float* __restrict__ out3) {
    __shared__ float w[8];
    int n = threadIdx.x;
    if (n < 8) w[n] = d_wfin[n];
    __syncthreads();
    float fl = flag[n];
    int ia = d_topI[0][n][0], ib = d_topI[0][n][1];
    int ic = d_topI[1][n][0], idd = d_topI[1][n][1];
    int cbase = blockIdx.x * 8;
    #pragma unroll
    for (int cc = 0; cc < 8; cc++) {
        int c = cbase + cc;
        const float* Kr = K + c * NN;
        const float* Gr = G + c * NN;
        float v = 0.f;
        if (fl == 1.0f)
            v = w[0] * Kr[ia] + w[1] * Kr[ib] + w[2] * Gr[ic] + w[3] * Gr[idd];
        if (n == 0)
            v += w[4] * Kr[0] + w[5] * Kr[0] + w[6] * Gr[0] + w[7] * Gr[0];
        out3[c * NN + n] = v;
    }
}

// ---------------- launch --------------------------------------------------
extern "C" void kernel_launch(void* const* d_in, const int* in_sizes, int n_in,
                              void* d_out, int out_size) {
    (void)in_sizes; (void)n_in; (void)out_size;
    const float* G = (const float*)d_in[0];   // generated (1,4096,32,32)
    const float* K = (const float*)d_in[1];   // known
    const float* M = (const float*)d_in[2];   // mask -> flag[1024]
    float* out = (float*)d_out;

    cudaFuncSetAttribute(k_gemm_mma, cudaFuncAttributeMaxDynamicSharedMemorySize, SMEM_GEMM);

    k_init<<<4, 256>>>();
    k_prep<<<dim3(32, 128, 2), dim3(32, 8)>>>(G, K, out);
    k_gemm_mma<<<100, 512, SMEM_GEMM>>>(M);
    k_topk<<<2048, 256>>>(M);
    k_finalize<<<1, 256>>>(M);
    k_rtn<<<512, 1024>>>(G, K, M, out + (size_t)2 * CN);
}